// round 16
// baseline (speedup 1.0000x reference)
#include <cuda_runtime.h>
#include <cuda_bf16.h>
#include <cuda_fp16.h>
#include <math.h>
#include <stdint.h>

#define NB    4
#define CCH   128
#define HW    4096            // 64*64 after 2x2 pool
#define KNN   16
#define PAIRS 65536           // HW*KNN per batch
#define NEGINF (-3.4e38f)

// ======================= helpers =======================
__device__ __forceinline__ uint32_t smem_u32(const void* p) {
    uint32_t a;
    asm("{ .reg .u64 t; cvta.to.shared.u64 t, %1; cvt.u32.u64 %0, t; }" : "=r"(a) : "l"(p));
    return a;
}
__device__ __forceinline__ void ldm_x4(uint32_t* r, uint32_t a) {
    asm volatile("ldmatrix.sync.aligned.m8n8.x4.shared.b16 {%0,%1,%2,%3}, [%4];"
        : "=r"(r[0]), "=r"(r[1]), "=r"(r[2]), "=r"(r[3]) : "r"(a));
}
__device__ __forceinline__ void mma_bf16(float* c, const uint32_t* a, const uint32_t* b) {
    asm volatile("mma.sync.aligned.m16n8k16.row.col.f32.bf16.bf16.f32 "
        "{%0,%1,%2,%3}, {%4,%5,%6,%7}, {%8,%9}, {%0,%1,%2,%3};"
        : "+f"(c[0]), "+f"(c[1]), "+f"(c[2]), "+f"(c[3])
        : "r"(a[0]), "r"(a[1]), "r"(a[2]), "r"(a[3]), "r"(b[0]), "r"(b[1]));
}
// monotone order-preserving transform on a packed pair of fp16:
// negative -> ~h, positive -> h | 0x8000 (per 16-bit half)
__device__ __forceinline__ uint32_t order_h2(uint32_t u) {
    return u ^ ((((u >> 15) & 0x00010001u) * 0xFFFFu) | 0x80008000u);
}
__device__ __forceinline__ uint32_t h2u(__half2 h) {
    union { __half2 h; uint32_t u; } c; c.h = h; return c.u;
}

// ======================= scratch (device globals) =======================
__device__ __align__(16) float g_pool[2][NB * CCH * HW];
__device__ __align__(16) float g_xt  [2][HW * CCH];                 // batch 0 only
__device__ __align__(16) __nv_bfloat16 g_xh[2][NB * HW * CCH];
__device__ __align__(16) float g_diag[2][NB * HW];
__device__ __align__(16) uint32_t g_scoreso[2][(size_t)NB * HW * HW / 2]; // ordered u16 pairs
__device__              int   g_knn [2][NB * PAIRS];
__device__ __align__(16) float g_AB  [4][HW * CCH];
__device__ __align__(16) float g_partial[1024][256];
__device__ __align__(16) float g_p2[64][256];
__device__ __align__(16) float g_gate[NB * CCH];

// ---------------- 1) fused maxpool + transpose + normalize ----------------
__global__ void __launch_bounds__(256) k_tnorm(const float* __restrict__ rgb,
                                               const float* __restrict__ ir) {
    __shared__ float s[128][33];
    int mod = blockIdx.z, n = blockIdx.y, hw0 = blockIdx.x * 32;
    const float* src = (mod == 0) ? rgb : ir;
    int y = hw0 >> 6, x0 = hw0 & 63;
    float* pooldst = g_pool[mod] + (size_t)n * CCH * HW;
#pragma unroll
    for (int p = 0; p < 16; p++) {
        int i = threadIdx.x + 256 * p;      // 128c x 32x
        int c = i >> 5, xl = i & 31;
        size_t base = ((size_t)(n * CCH + c) * 128 + 2 * y) * 128 + 2 * (x0 + xl);
        float2 u = *(const float2*)(src + base);
        float2 v = *(const float2*)(src + base + 128);
        float pv = fmaxf(fmaxf(u.x, u.y), fmaxf(v.x, v.y));
        s[c][xl] = pv;
        pooldst[(size_t)c * HW + hw0 + xl] = pv;
    }
    __syncthreads();
    int w = threadIdx.x >> 5, l = threadIdx.x & 31;
#pragma unroll
    for (int m = 0; m < 4; m++) {
        int hw = w * 4 + m;
        float a0 = s[l][hw], a1 = s[l + 32][hw], a2 = s[l + 64][hw], a3 = s[l + 96][hw];
        float ss = a0 * a0 + a1 * a1 + a2 * a2 + a3 * a3;
#pragma unroll
        for (int off = 16; off > 0; off >>= 1) ss += __shfl_xor_sync(0xffffffff, ss, off);
        float inv = 1.0f / fmaxf(sqrtf(ss), 1e-12f);
        union { __nv_bfloat16 b[2]; uint32_t u; } w0, w1;
        w0.b[0] = __float2bfloat16_rn(s[2 * l][hw] * inv);
        w0.b[1] = __float2bfloat16_rn(s[2 * l + 1][hw] * inv);
        w1.b[0] = __float2bfloat16_rn(s[2 * l + 64][hw] * inv);
        w1.b[1] = __float2bfloat16_rn(s[2 * l + 65][hw] * inv);
        uint32_t* dst = (uint32_t*)(g_xh[mod] + (size_t)(n * HW + hw0 + hw) * CCH);
        dst[l] = w0.u;
        dst[l + 32] = w1.u;
        if (n == 0) {
            float* xd = g_xt[mod] + (size_t)(hw0 + hw) * CCH;
            xd[l] = a0; xd[l + 32] = a1; xd[l + 64] = a2; xd[l + 96] = a3;
        }
        if (l == 0) g_diag[mod][n * HW + hw0 + hw] = ss * inv * inv;
    }
}

// ---------------- 2) triangular bf16 gram -> ordered-u16 scores ----------------
#define TILE_STRIDE_B 272                 // 136 bf16 * 2
#define TILE_BYTES    (128 * TILE_STRIDE_B)
#define GS_DIAGA 0
#define GS_DIAGB 512
#define GS_AH    1024
#define GS_BH    (GS_AH + TILE_BYTES)
#define GS_SC    1024                     // fp16 overlay 128 x 130 halves = 33280 B
#define SC_STR   130
#define GS_TOTAL (GS_AH + 2 * TILE_BYTES)   // 70656 B

__global__ void __launch_bounds__(256, 2) k_gram_tri() {
    extern __shared__ char smem[];
    uint32_t sb = smem_u32(smem);
    int tid = threadIdx.x, lane = tid & 31, w = tid >> 5;
    int t = blockIdx.x;
    int mod = blockIdx.y >> 2, n = blockIdx.y & 3;

    int by = (int)((sqrtf(8.0f * t + 1.0f) - 1.0f) * 0.5f);
    while ((by + 1) * (by + 2) / 2 <= t) by++;
    while (by * (by + 1) / 2 > t) by--;
    int bx = t - by * (by + 1) / 2;       // bx <= by

    const __nv_bfloat16* XH = g_xh[mod];
    int rowA0 = n * HW + by * 128;
    int rowB0 = n * HW + bx * 128;

    for (int i = tid; i < 2048; i += 256) {
        int r = i >> 4, ch = i & 15;
        uint32_t so = (uint32_t)r * TILE_STRIDE_B + (uint32_t)ch * 16u;
        *(uint4*)(smem + GS_AH + so) = *((const uint4*)(XH + (size_t)(rowA0 + r) * CCH) + ch);
        *(uint4*)(smem + GS_BH + so) = *((const uint4*)(XH + (size_t)(rowB0 + r) * CCH) + ch);
    }
    if (tid < 128)      ((float*)(smem + GS_DIAGA))[tid] = g_diag[mod][n * HW + by * 128 + tid];
    else                ((float*)(smem + GS_DIAGB))[tid - 128] =
                            g_diag[mod][n * HW + bx * 128 + (tid - 128)];
    __syncthreads();

    int wm = w >> 1, wn = w & 1;
    int m_base = wm * 32, n_base = wn * 64;

    float acc[2][8][4];
#pragma unroll
    for (int mf = 0; mf < 2; mf++)
#pragma unroll
        for (int nf = 0; nf < 8; nf++)
#pragma unroll
            for (int q = 0; q < 4; q++) acc[mf][nf][q] = 0.0f;

    int arow  = lane & 15;
    int acol8 = (lane >> 4) << 3;
    int brow  = ((lane >> 4) << 3) + (lane & 7);
    int bcol8 = ((lane >> 3) & 1) << 3;

    uint32_t aaddr = sb + GS_AH + (uint32_t)(m_base + arow) * TILE_STRIDE_B + (uint32_t)acol8 * 2u;
    uint32_t baddr = sb + GS_BH + (uint32_t)(n_base + brow) * TILE_STRIDE_B + (uint32_t)bcol8 * 2u;

#pragma unroll
    for (int k0 = 0; k0 < 128; k0 += 16) {
        uint32_t a[2][4], b[4][4];
        ldm_x4(a[0], aaddr + (uint32_t)k0 * 2u);
        ldm_x4(a[1], aaddr + 16u * TILE_STRIDE_B + (uint32_t)k0 * 2u);
#pragma unroll
        for (int q = 0; q < 4; q++)
            ldm_x4(b[q], baddr + (uint32_t)(q * 16) * TILE_STRIDE_B + (uint32_t)k0 * 2u);
#pragma unroll
        for (int mf = 0; mf < 2; mf++)
#pragma unroll
            for (int nf = 0; nf < 8; nf++)
                mma_bf16(acc[mf][nf], a[mf], &b[nf >> 1][(nf & 1) * 2]);
    }

    __syncthreads();   // operands dead; overlay with raw g (fp16)

    {
        __half* sch = (__half*)(smem + GS_SC);
        int r_in  = lane >> 2;
        int cpair = (lane & 3) * 2;
#pragma unroll
        for (int mf = 0; mf < 2; mf++) {
            int rl = m_base + mf * 16 + r_in;
#pragma unroll
            for (int nf = 0; nf < 8; nf++) {
                int col = n_base + nf * 8 + cpair;
                *(__half2*)(sch + rl * SC_STR + col) =
                    __floats2half2_rn(acc[mf][nf][0], acc[mf][nf][1]);
                *(__half2*)(sch + (rl + 8) * SC_STR + col) =
                    __floats2half2_rn(acc[mf][nf][2], acc[mf][nf][3]);
            }
        }
    }
    __syncthreads();

    const __half* sch = (const __half*)(smem + GS_SC);
    const float* dA = (const float*)(smem + GS_DIAGA);
    const float* dB = (const float*)(smem + GS_DIAGB);
    uint32_t* G = g_scoreso[mod] + (size_t)n * HW * HW / 2;

    // direct: rows in by-block, cols in bx-block (store ordered-u16 pairs)
#pragma unroll 1
    for (int rr = 0; rr < 16; rr++) {
        int i = w * 16 + rr;
        float2 f0 = __half22float2(*(const __half2*)(sch + i * SC_STR + 2 * lane));
        float2 f1 = __half22float2(*(const __half2*)(sch + i * SC_STR + 2 * lane + 64));
        uint32_t h0 = order_h2(h2u(__floats2half2_rn(2.0f * f0.x - dB[2 * lane],
                                                     2.0f * f0.y - dB[2 * lane + 1])));
        uint32_t h1 = order_h2(h2u(__floats2half2_rn(2.0f * f1.x - dB[2 * lane + 64],
                                                     2.0f * f1.y - dB[2 * lane + 65])));
        uint32_t* dst = G + ((size_t)(by * 128 + i) * HW + bx * 128) / 2;
        dst[lane] = h0;
        dst[lane + 32] = h1;
    }
    // mirror: column-pair reads cover two output rows per iteration
    if (bx != by) {
#pragma unroll 1
        for (int p = 0; p < 8; p++) {
            int j = w * 16 + 2 * p;
            float2 ga = __half22float2(*(const __half2*)(sch + (2 * lane) * SC_STR + j));
            float2 gb = __half22float2(*(const __half2*)(sch + (2 * lane + 1) * SC_STR + j));
            float2 gc = __half22float2(*(const __half2*)(sch + (2 * lane + 64) * SC_STR + j));
            float2 gd = __half22float2(*(const __half2*)(sch + (2 * lane + 65) * SC_STR + j));
            float da0 = dA[2 * lane], da1 = dA[2 * lane + 1];
            float da2 = dA[2 * lane + 64], da3 = dA[2 * lane + 65];
            uint32_t r0 = order_h2(h2u(__floats2half2_rn(2.0f * ga.x - da0, 2.0f * gb.x - da1)));
            uint32_t r1 = order_h2(h2u(__floats2half2_rn(2.0f * gc.x - da2, 2.0f * gd.x - da3)));
            uint32_t* d0 = G + ((size_t)(bx * 128 + j) * HW + by * 128) / 2;
            d0[lane] = r0;
            d0[lane + 32] = r1;
            uint32_t s0 = order_h2(h2u(__floats2half2_rn(2.0f * ga.y - da0, 2.0f * gb.y - da1)));
            uint32_t s1 = order_h2(h2u(__floats2half2_rn(2.0f * gc.y - da2, 2.0f * gd.y - da3)));
            uint32_t* d1 = G + ((size_t)(bx * 128 + j + 1) * HW + by * 128) / 2;
            d1[lane] = s0;
            d1[lane + 32] = s1;
        }
    }
}

// ---------------- 3) per-row top-16: warp-autonomous two-phase selection ----------------
// key = (ordered_u16 << 12) | (4095 - j); phase 1 = per-warp top-16 of 512-elem slice
// (no barriers), phase 2 = warp 0 merges 128 candidates (1 barrier total).
__global__ void __launch_bounds__(256) k_topk() {
    __shared__ uint32_t sc[HW];        // 16KB keys
    __shared__ uint32_t cand[128];     // 8 warps x 16 candidates
    int mod = blockIdx.z, n = blockIdx.y, i = blockIdx.x;
    int t = threadIdx.x, w = t >> 5, l = t & 31;
    const uint4* S4 = (const uint4*)(g_scoreso[mod]
                        + ((size_t)n * HW * HW + (size_t)i * HW) / 2);

    // thread owns 16 contiguous elements: j in [w*512 + l*16, +16)
    int jbase = w * 512 + l * 16;
    uint32_t myMax = 0;
#pragma unroll
    for (int step = 0; step < 2; step++) {
        int v = (jbase >> 3) + step;          // uint4 index (8 halves per uint4)
        uint4 p2 = S4[v];
        int j0 = v * 8;
        uint32_t base = (uint32_t)(4095 - j0);
        uint32_t pw[4] = { p2.x, p2.y, p2.z, p2.w };
#pragma unroll
        for (int q = 0; q < 4; q++) {
            int j = j0 + 2 * q;
            uint32_t k0 = ((pw[q] & 0xFFFFu) << 12) | (base - 2 * q);
            uint32_t k1 = ((pw[q] >> 4) & 0x0FFFF000u) | (base - 2 * q - 1);
            sc[j] = k0; sc[j + 1] = k1;
            myMax = max(myMax, max(k0, k1));
        }
    }
    // phase 1: warp-local top-16 (no block barriers)
    uint32_t mySel = 0;
#pragma unroll 1
    for (int s = 0; s < KNN; s++) {
        uint32_t B = __reduce_max_sync(0xffffffffu, myMax);
        if (l == s) mySel = B;
        if (myMax == B) {                     // unique owner (index in key)
            sc[4095 - (int)(B & 0xFFFu)] = 0;
            uint32_t nm = 0;
#pragma unroll
            for (int q = 0; q < 16; q++) nm = max(nm, sc[jbase + q]);
            myMax = nm;
        }
    }
    if (l < KNN) cand[w * KNN + l] = mySel;
    __syncthreads();

    // phase 2: warp 0 merges 128 candidates -> global top-16
    if (w == 0) {
        uint32_t c0 = cand[l], c1 = cand[l + 32], c2 = cand[l + 64], c3 = cand[l + 96];
        uint32_t msel = 0;
#pragma unroll 1
        for (int s = 0; s < KNN; s++) {
            uint32_t m = max(max(c0, c1), max(c2, c3));
            uint32_t B = __reduce_max_sync(0xffffffffu, m);
            if (l == s) msel = B;
            if (c0 == B) c0 = 0;
            if (c1 == B) c1 = 0;
            if (c2 == B) c2 = 0;
            if (c3 == B) c3 = 0;
        }
        int* out = g_knn[mod] + ((size_t)n * HW + i) * KNN;
        if (l < KNN) out[l] = 4095 - (int)(msel & 0xFFFu);
    }
}

// ---------------- 4) A/B tables ----------------
__global__ __launch_bounds__(256) void k_ab(const float* __restrict__ Wr,
                                            const float* __restrict__ Wi) {
    __shared__ float Xs[64][36];
    __shared__ float Ws[32][128];
    int which = blockIdx.y;
    const float* X  = (which == 0 || which == 3) ? g_xt[0] : g_xt[1];
    const float* Wg = (which < 2) ? Wr : Wi;
    bool both = (which == 0 || which == 2);
    int r0 = blockIdx.x * 64;
    int tx = threadIdx.x & 15, ty = threadIdx.x >> 4;

    float acc[4][8];
#pragma unroll
    for (int i = 0; i < 4; i++)
#pragma unroll
        for (int j = 0; j < 8; j++) acc[i][j] = 0.0f;

    for (int k0 = 0; k0 < 128; k0 += 32) {
#pragma unroll
        for (int p = 0; p < 2; p++) {
            int f4 = threadIdx.x + 256 * p;
            int r = f4 >> 3, kq = f4 & 7;
            *(float4*)(&Xs[r][kq * 4]) =
                *(const float4*)(X + (size_t)(r0 + r) * CCH + k0 + kq * 4);
        }
#pragma unroll
        for (int p = 0; p < 4; p++) {
            int f4 = threadIdx.x + 256 * p;
            int kk = f4 >> 5, cq = f4 & 31;
            float4 w = *(const float4*)(Wg + (size_t)(128 + k0 + kk) * CCH + cq * 4);
            if (both) {
                float4 w0 = *(const float4*)(Wg + (size_t)(k0 + kk) * CCH + cq * 4);
                w.x += w0.x; w.y += w0.y; w.z += w0.z; w.w += w0.w;
            }
            *(float4*)(&Ws[kk][cq * 4]) = w;
        }
        __syncthreads();
#pragma unroll 8
        for (int kk = 0; kk < 32; kk++) {
            float a[4], b[8];
#pragma unroll
            for (int i = 0; i < 4; i++) a[i] = Xs[ty + 16 * i][kk];
#pragma unroll
            for (int j = 0; j < 8; j++) b[j] = Ws[kk][tx + 16 * j];
#pragma unroll
            for (int i = 0; i < 4; i++)
#pragma unroll
                for (int j = 0; j < 8; j++) acc[i][j] += a[i] * b[j];
        }
        __syncthreads();
    }
#pragma unroll
    for (int i = 0; i < 4; i++)
#pragma unroll
        for (int j = 0; j < 8; j++)
            g_AB[which][(size_t)(r0 + ty + 16 * i) * CCH + tx + 16 * j] = acc[i][j];
}

// ---------------- 5) pair gather-mean ----------------
__global__ __launch_bounds__(128) void k_pair(const float* __restrict__ br,
                                              const float* __restrict__ bi) {
    __shared__ int sp[256], sq[256];
    int n = blockIdx.y;
    int base = n * PAIRS + blockIdx.x * 256;
    for (int t = threadIdx.x; t < 256; t += 128) {
        sp[t] = g_knn[0][base + t];
        sq[t] = g_knn[1][base + t];
    }
    __syncthreads();
    int c = threadIdx.x;
    float brc = br[c], bic = bi[c];
    float aR = 0.0f, aI = 0.0f;
#pragma unroll 4
    for (int t = 0; t < 256; t++) {
        int p = sp[t], q = sq[t];
        float fr = g_AB[0][p * CCH + c] - g_AB[1][q * CCH + c] + brc;
        aR += (fr >= 0.0f) ? fr : 0.01f * fr;
        float fi = g_AB[2][q * CCH + c] - g_AB[3][p * CCH + c] + bic;
        aI += (fi >= 0.0f) ? fi : 0.01f * fi;
    }
    int b = n * 256 + blockIdx.x;
    g_partial[b][c]       = aR;
    g_partial[b][c + 128] = aI;
}

// ---------------- 6) first-level reduce: 256 partials -> 16 per n ----------------
__global__ void k_reduce16() {
    int b = blockIdx.x;                 // 64 blocks: n = b>>4, group = b&15
    int n = b >> 4, r0 = (b & 15) * 16;
    int d = threadIdx.x;
    float s = 0.0f;
#pragma unroll
    for (int r = 0; r < 16; r++) s += g_partial[n * 256 + r0 + r][d];
    g_p2[b][d] = s;
}

// ---------------- 7) final reduce + SE gate ----------------
__global__ void k_se(const float* __restrict__ w1, const float* __restrict__ b1,
                     const float* __restrict__ w2, const float* __restrict__ b2) {
    __shared__ float m_s[1024];
    __shared__ float tm[NB][8];
    int tid = threadIdx.x;              // 512
#pragma unroll
    for (int it = 0; it < 2; it++) {
        int idx = tid + 512 * it;
        int n = idx >> 8, d = idx & 255;
        float s = 0.0f;
#pragma unroll
        for (int g = 0; g < 16; g++) s += g_p2[n * 16 + g][d];
        m_s[idx] = s * (1.0f / (float)PAIRS);
    }
    __syncthreads();
    if (tid < 32) {
        int n = tid >> 3, j = tid & 7;
        float s = b1[j];
        for (int d = 0; d < 256; d++) s += m_s[n * 256 + d] * w1[d * 8 + j];
        tm[n][j] = (s >= 0.0f) ? s : 0.01f * s;
    }
    __syncthreads();
    int n = tid >> 7, c = tid & 127;
    float s = b2[c];
#pragma unroll
    for (int j = 0; j < 8; j++) s += tm[n][j] * w2[j * 128 + c];
    g_gate[n * 128 + c] = 1.0f / (1.0f + expf(-s));
}

// ---------------- 8) gated blend + relu ----------------
__global__ void k_out(const float* __restrict__ g1, const float* __restrict__ g2,
                      float* __restrict__ out) {
    int o = blockIdx.x * blockDim.x + threadIdx.x;
    if (o >= NB * CCH * HW) return;
    int nc = o >> 12;
    float g = g_gate[nc];
    float v = g1[0] * g * g_pool[0][o] + g2[0] * (1.0f - g) * g_pool[1][o];
    out[o] = fmaxf(v, 0.0f);
}

// ---------------- launch ----------------
extern "C" void kernel_launch(void* const* d_in, const int* in_sizes, int n_in,
                              void* d_out, int out_size) {
    const float* rgb = (const float*)d_in[0];
    const float* ir  = (const float*)d_in[1];
    const float* Wr  = (const float*)d_in[2];
    const float* br  = (const float*)d_in[3];
    const float* Wi  = (const float*)d_in[4];
    const float* bi  = (const float*)d_in[5];
    const float* w1  = (const float*)d_in[6];
    const float* b1  = (const float*)d_in[7];
    const float* w2  = (const float*)d_in[8];
    const float* b2  = (const float*)d_in[9];
    const float* g1  = (const float*)d_in[10];
    const float* g2  = (const float*)d_in[11];
    float* out = (float*)d_out;

    cudaFuncSetAttribute(k_gram_tri, cudaFuncAttributeMaxDynamicSharedMemorySize, GS_TOTAL);

    k_tnorm<<<dim3(128, 4, 2), 256>>>(rgb, ir);   // fused pool+transpose+norm
    k_ab<<<dim3(64, 4), 256>>>(Wr, Wi);

    k_gram_tri<<<dim3(528, 8), 256, GS_TOTAL>>>();   // triangular, ordered-u16 scores
    k_topk<<<dim3(4096, 4, 2), 256>>>();             // warp-autonomous two-phase top-16

    k_pair<<<dim3(256, 4), 128>>>(br, bi);
    k_reduce16<<<64, 256>>>();
    k_se<<<1, 512>>>(w1, b1, w2, b2);
    k_out<<<8192, 256>>>(g1, g2, out);
}

// round 17
// speedup vs baseline: 1.0781x; 1.0781x over previous
#include <cuda_runtime.h>
#include <cuda_bf16.h>
#include <cuda_fp16.h>
#include <math.h>
#include <stdint.h>

#define NB    4
#define CCH   128
#define HW    4096            // 64*64 after 2x2 pool
#define KNN   16
#define PAIRS 65536           // HW*KNN per batch
#define NEGINF (-3.4e38f)

// ======================= helpers =======================
__device__ __forceinline__ uint32_t smem_u32(const void* p) {
    uint32_t a;
    asm("{ .reg .u64 t; cvta.to.shared.u64 t, %1; cvt.u32.u64 %0, t; }" : "=r"(a) : "l"(p));
    return a;
}
__device__ __forceinline__ void ldm_x4(uint32_t* r, uint32_t a) {
    asm volatile("ldmatrix.sync.aligned.m8n8.x4.shared.b16 {%0,%1,%2,%3}, [%4];"
        : "=r"(r[0]), "=r"(r[1]), "=r"(r[2]), "=r"(r[3]) : "r"(a));
}
__device__ __forceinline__ void mma_bf16(float* c, const uint32_t* a, const uint32_t* b) {
    asm volatile("mma.sync.aligned.m16n8k16.row.col.f32.bf16.bf16.f32 "
        "{%0,%1,%2,%3}, {%4,%5,%6,%7}, {%8,%9}, {%0,%1,%2,%3};"
        : "+f"(c[0]), "+f"(c[1]), "+f"(c[2]), "+f"(c[3])
        : "r"(a[0]), "r"(a[1]), "r"(a[2]), "r"(a[3]), "r"(b[0]), "r"(b[1]));
}
// monotone order-preserving transform on a packed pair of fp16:
// negative -> ~h, positive -> h | 0x8000 (per 16-bit half)
__device__ __forceinline__ uint32_t order_h2(uint32_t u) {
    return u ^ ((((u >> 15) & 0x00010001u) * 0xFFFFu) | 0x80008000u);
}
__device__ __forceinline__ uint32_t h2u(__half2 h) {
    union { __half2 h; uint32_t u; } c; c.h = h; return c.u;
}

// ======================= scratch (device globals) =======================
__device__ __align__(16) float g_pool[2][NB * CCH * HW];
__device__ __align__(16) float g_xt  [2][HW * CCH];                 // batch 0 only
__device__ __align__(16) __nv_bfloat16 g_xh[2][NB * HW * CCH];
__device__ __align__(16) float g_diag[2][NB * HW];
__device__ __align__(16) uint32_t g_scoreso[2][(size_t)NB * HW * HW / 2]; // ordered u16 pairs
__device__              int   g_knn [2][NB * PAIRS];
__device__ __align__(16) float g_AB  [4][HW * CCH];
__device__ __align__(16) float g_partial[1024][256];
__device__ __align__(16) float g_p2[64][256];
__device__ __align__(16) float g_gate[NB * CCH];

// ---------------- 1) fused maxpool + transpose + normalize ----------------
__global__ void __launch_bounds__(256) k_tnorm(const float* __restrict__ rgb,
                                               const float* __restrict__ ir) {
    __shared__ float s[128][33];
    int mod = blockIdx.z, n = blockIdx.y, hw0 = blockIdx.x * 32;
    const float* src = (mod == 0) ? rgb : ir;
    int y = hw0 >> 6, x0 = hw0 & 63;
    float* pooldst = g_pool[mod] + (size_t)n * CCH * HW;
#pragma unroll
    for (int p = 0; p < 16; p++) {
        int i = threadIdx.x + 256 * p;      // 128c x 32x
        int c = i >> 5, xl = i & 31;
        size_t base = ((size_t)(n * CCH + c) * 128 + 2 * y) * 128 + 2 * (x0 + xl);
        float2 u = *(const float2*)(src + base);
        float2 v = *(const float2*)(src + base + 128);
        float pv = fmaxf(fmaxf(u.x, u.y), fmaxf(v.x, v.y));
        s[c][xl] = pv;
        pooldst[(size_t)c * HW + hw0 + xl] = pv;
    }
    __syncthreads();
    int w = threadIdx.x >> 5, l = threadIdx.x & 31;
#pragma unroll
    for (int m = 0; m < 4; m++) {
        int hw = w * 4 + m;
        float a0 = s[l][hw], a1 = s[l + 32][hw], a2 = s[l + 64][hw], a3 = s[l + 96][hw];
        float ss = a0 * a0 + a1 * a1 + a2 * a2 + a3 * a3;
#pragma unroll
        for (int off = 16; off > 0; off >>= 1) ss += __shfl_xor_sync(0xffffffff, ss, off);
        float inv = 1.0f / fmaxf(sqrtf(ss), 1e-12f);
        union { __nv_bfloat16 b[2]; uint32_t u; } w0, w1;
        w0.b[0] = __float2bfloat16_rn(s[2 * l][hw] * inv);
        w0.b[1] = __float2bfloat16_rn(s[2 * l + 1][hw] * inv);
        w1.b[0] = __float2bfloat16_rn(s[2 * l + 64][hw] * inv);
        w1.b[1] = __float2bfloat16_rn(s[2 * l + 65][hw] * inv);
        uint32_t* dst = (uint32_t*)(g_xh[mod] + (size_t)(n * HW + hw0 + hw) * CCH);
        dst[l] = w0.u;
        dst[l + 32] = w1.u;
        if (n == 0) {
            float* xd = g_xt[mod] + (size_t)(hw0 + hw) * CCH;
            xd[l] = a0; xd[l + 32] = a1; xd[l + 64] = a2; xd[l + 96] = a3;
        }
        if (l == 0) g_diag[mod][n * HW + hw0 + hw] = ss * inv * inv;
    }
}

// ---------------- 2) merged: triangular bf16 gram (y<8) + A/B tables (y==8) --------
#define TILE_STRIDE_B 272                 // 136 bf16 * 2
#define TILE_BYTES    (128 * TILE_STRIDE_B)
#define GS_DIAGA 0
#define GS_DIAGB 512
#define GS_AH    1024
#define GS_BH    (GS_AH + TILE_BYTES)
#define GS_SC    1024                     // fp16 overlay 128 x 130 halves = 33280 B
#define SC_STR   130
#define GS_TOTAL (GS_AH + 2 * TILE_BYTES)   // 70656 B

__global__ void __launch_bounds__(256, 2) k_gram_tri(const float* __restrict__ Wr,
                                                     const float* __restrict__ Wi) {
    extern __shared__ char smem[];
    uint32_t sb = smem_u32(smem);
    int tid = threadIdx.x, lane = tid & 31, w = tid >> 5;

    // ---------- A/B table blocks (overlapped with gram) ----------
    if (blockIdx.y == 8) {
        if (blockIdx.x >= 256) return;
        float* Xs = (float*)smem;                        // [64][36]
        float* Ws = (float*)(smem + 64 * 36 * 4);        // [32][128]
        int which = blockIdx.x >> 6;
        const float* X  = (which == 0 || which == 3) ? g_xt[0] : g_xt[1];
        const float* Wg = (which < 2) ? Wr : Wi;
        bool both = (which == 0 || which == 2);
        int r0 = (blockIdx.x & 63) * 64;
        int tx = tid & 15, ty = tid >> 4;

        float acc[4][8];
#pragma unroll
        for (int i = 0; i < 4; i++)
#pragma unroll
            for (int j = 0; j < 8; j++) acc[i][j] = 0.0f;

        for (int k0 = 0; k0 < 128; k0 += 32) {
#pragma unroll
            for (int p = 0; p < 2; p++) {
                int f4 = tid + 256 * p;
                int r = f4 >> 3, kq = f4 & 7;
                *(float4*)(&Xs[r * 36 + kq * 4]) =
                    *(const float4*)(X + (size_t)(r0 + r) * CCH + k0 + kq * 4);
            }
#pragma unroll
            for (int p = 0; p < 4; p++) {
                int f4 = tid + 256 * p;
                int kk = f4 >> 5, cq = f4 & 31;
                float4 wv = *(const float4*)(Wg + (size_t)(128 + k0 + kk) * CCH + cq * 4);
                if (both) {
                    float4 w0 = *(const float4*)(Wg + (size_t)(k0 + kk) * CCH + cq * 4);
                    wv.x += w0.x; wv.y += w0.y; wv.z += w0.z; wv.w += w0.w;
                }
                *(float4*)(&Ws[kk * 128 + cq * 4]) = wv;
            }
            __syncthreads();
#pragma unroll 8
            for (int kk = 0; kk < 32; kk++) {
                float a[4], b[8];
#pragma unroll
                for (int i = 0; i < 4; i++) a[i] = Xs[(ty + 16 * i) * 36 + kk];
#pragma unroll
                for (int j = 0; j < 8; j++) b[j] = Ws[kk * 128 + tx + 16 * j];
#pragma unroll
                for (int i = 0; i < 4; i++)
#pragma unroll
                    for (int j = 0; j < 8; j++) acc[i][j] += a[i] * b[j];
            }
            __syncthreads();
        }
#pragma unroll
        for (int i = 0; i < 4; i++)
#pragma unroll
            for (int j = 0; j < 8; j++)
                g_AB[which][(size_t)(r0 + ty + 16 * i) * CCH + tx + 16 * j] = acc[i][j];
        return;
    }

    // ---------- gram tiles ----------
    int t = blockIdx.x;
    int mod = blockIdx.y >> 2, n = blockIdx.y & 3;

    int by = (int)((sqrtf(8.0f * t + 1.0f) - 1.0f) * 0.5f);
    while ((by + 1) * (by + 2) / 2 <= t) by++;
    while (by * (by + 1) / 2 > t) by--;
    int bx = t - by * (by + 1) / 2;       // bx <= by

    const __nv_bfloat16* XH = g_xh[mod];
    int rowA0 = n * HW + by * 128;
    int rowB0 = n * HW + bx * 128;

    for (int i = tid; i < 2048; i += 256) {
        int r = i >> 4, ch = i & 15;
        uint32_t so = (uint32_t)r * TILE_STRIDE_B + (uint32_t)ch * 16u;
        *(uint4*)(smem + GS_AH + so) = *((const uint4*)(XH + (size_t)(rowA0 + r) * CCH) + ch);
        *(uint4*)(smem + GS_BH + so) = *((const uint4*)(XH + (size_t)(rowB0 + r) * CCH) + ch);
    }
    if (tid < 128)      ((float*)(smem + GS_DIAGA))[tid] = g_diag[mod][n * HW + by * 128 + tid];
    else                ((float*)(smem + GS_DIAGB))[tid - 128] =
                            g_diag[mod][n * HW + bx * 128 + (tid - 128)];
    __syncthreads();

    int wm = w >> 1, wn = w & 1;
    int m_base = wm * 32, n_base = wn * 64;

    float acc[2][8][4];
#pragma unroll
    for (int mf = 0; mf < 2; mf++)
#pragma unroll
        for (int nf = 0; nf < 8; nf++)
#pragma unroll
            for (int q = 0; q < 4; q++) acc[mf][nf][q] = 0.0f;

    int arow  = lane & 15;
    int acol8 = (lane >> 4) << 3;
    int brow  = ((lane >> 4) << 3) + (lane & 7);
    int bcol8 = ((lane >> 3) & 1) << 3;

    uint32_t aaddr = sb + GS_AH + (uint32_t)(m_base + arow) * TILE_STRIDE_B + (uint32_t)acol8 * 2u;
    uint32_t baddr = sb + GS_BH + (uint32_t)(n_base + brow) * TILE_STRIDE_B + (uint32_t)bcol8 * 2u;

#pragma unroll
    for (int k0 = 0; k0 < 128; k0 += 16) {
        uint32_t a[2][4], b[4][4];
        ldm_x4(a[0], aaddr + (uint32_t)k0 * 2u);
        ldm_x4(a[1], aaddr + 16u * TILE_STRIDE_B + (uint32_t)k0 * 2u);
#pragma unroll
        for (int q = 0; q < 4; q++)
            ldm_x4(b[q], baddr + (uint32_t)(q * 16) * TILE_STRIDE_B + (uint32_t)k0 * 2u);
#pragma unroll
        for (int mf = 0; mf < 2; mf++)
#pragma unroll
            for (int nf = 0; nf < 8; nf++)
                mma_bf16(acc[mf][nf], a[mf], &b[nf >> 1][(nf & 1) * 2]);
    }

    __syncthreads();   // operands dead; overlay with raw g (fp16)

    {
        __half* sch = (__half*)(smem + GS_SC);
        int r_in  = lane >> 2;
        int cpair = (lane & 3) * 2;
#pragma unroll
        for (int mf = 0; mf < 2; mf++) {
            int rl = m_base + mf * 16 + r_in;
#pragma unroll
            for (int nf = 0; nf < 8; nf++) {
                int col = n_base + nf * 8 + cpair;
                *(__half2*)(sch + rl * SC_STR + col) =
                    __floats2half2_rn(acc[mf][nf][0], acc[mf][nf][1]);
                *(__half2*)(sch + (rl + 8) * SC_STR + col) =
                    __floats2half2_rn(acc[mf][nf][2], acc[mf][nf][3]);
            }
        }
    }
    __syncthreads();

    const __half* sch = (const __half*)(smem + GS_SC);
    const float* dA = (const float*)(smem + GS_DIAGA);
    const float* dB = (const float*)(smem + GS_DIAGB);
    uint32_t* G = g_scoreso[mod] + (size_t)n * HW * HW / 2;

    // direct: rows in by-block, cols in bx-block (store ordered-u16 pairs)
#pragma unroll 1
    for (int rr = 0; rr < 16; rr++) {
        int i = w * 16 + rr;
        float2 f0 = __half22float2(*(const __half2*)(sch + i * SC_STR + 2 * lane));
        float2 f1 = __half22float2(*(const __half2*)(sch + i * SC_STR + 2 * lane + 64));
        uint32_t h0 = order_h2(h2u(__floats2half2_rn(2.0f * f0.x - dB[2 * lane],
                                                     2.0f * f0.y - dB[2 * lane + 1])));
        uint32_t h1 = order_h2(h2u(__floats2half2_rn(2.0f * f1.x - dB[2 * lane + 64],
                                                     2.0f * f1.y - dB[2 * lane + 65])));
        uint32_t* dst = G + ((size_t)(by * 128 + i) * HW + bx * 128) / 2;
        dst[lane] = h0;
        dst[lane + 32] = h1;
    }
    // mirror: column-pair reads cover two output rows per iteration
    if (bx != by) {
#pragma unroll 1
        for (int p = 0; p < 8; p++) {
            int j = w * 16 + 2 * p;
            float2 ga = __half22float2(*(const __half2*)(sch + (2 * lane) * SC_STR + j));
            float2 gb = __half22float2(*(const __half2*)(sch + (2 * lane + 1) * SC_STR + j));
            float2 gc = __half22float2(*(const __half2*)(sch + (2 * lane + 64) * SC_STR + j));
            float2 gd = __half22float2(*(const __half2*)(sch + (2 * lane + 65) * SC_STR + j));
            float da0 = dA[2 * lane], da1 = dA[2 * lane + 1];
            float da2 = dA[2 * lane + 64], da3 = dA[2 * lane + 65];
            uint32_t r0 = order_h2(h2u(__floats2half2_rn(2.0f * ga.x - da0, 2.0f * gb.x - da1)));
            uint32_t r1 = order_h2(h2u(__floats2half2_rn(2.0f * gc.x - da2, 2.0f * gd.x - da3)));
            uint32_t* d0 = G + ((size_t)(bx * 128 + j) * HW + by * 128) / 2;
            d0[lane] = r0;
            d0[lane + 32] = r1;
            uint32_t s0 = order_h2(h2u(__floats2half2_rn(2.0f * ga.y - da0, 2.0f * gb.y - da1)));
            uint32_t s1 = order_h2(h2u(__floats2half2_rn(2.0f * gc.y - da2, 2.0f * gd.y - da3)));
            uint32_t* d1 = G + ((size_t)(bx * 128 + j + 1) * HW + by * 128) / 2;
            d1[lane] = s0;
            d1[lane + 32] = s1;
        }
    }
}

// ---------------- 3) per-row top-16: pre-ordered keys + REDUX (R13 measured-best) ----------------
// key = (ordered_u16 << 12) | (4095 - j)
__global__ void __launch_bounds__(256) k_topk() {
    __shared__ uint32_t sc[HW];     // 16KB keys
    __shared__ uint32_t wv[2][8];
    __shared__ uint32_t bc[2];
    int mod = blockIdx.z, n = blockIdx.y, i = blockIdx.x;
    int t = threadIdx.x, w = t >> 5, l = t & 31;
    const uint4* S4 = (const uint4*)(g_scoreso[mod]
                        + ((size_t)n * HW * HW + (size_t)i * HW) / 2);

    uint32_t myKey = 0;
#pragma unroll
    for (int step = 0; step < 2; step++) {
        int v = t + 256 * step;
        uint4 p2 = S4[v];               // 4 u32 = 8 ordered halves
        int j0 = v * 8;
        uint32_t base = (uint32_t)(4095 - j0);
        uint32_t pw[4] = { p2.x, p2.y, p2.z, p2.w };
#pragma unroll
        for (int q = 0; q < 4; q++) {
            int j = j0 + 2 * q;
            uint32_t k0 = ((pw[q] & 0xFFFFu) << 12) | (base - 2 * q);
            uint32_t k1 = ((pw[q] >> 4) & 0x0FFFF000u) | (base - 2 * q - 1);
            sc[j] = k0; sc[j + 1] = k1;
            myKey = max(myKey, max(k0, k1));
        }
    }
    __syncthreads();

    int* out = g_knn[mod] + ((size_t)n * HW + i) * KNN;
#pragma unroll 1
    for (int s = 0; s < KNN; s++) {
        int pb = s & 1;
        uint32_t wk = __reduce_max_sync(0xffffffffu, myKey);
        if (l == 0) wv[pb][w] = wk;
        __syncthreads();
        if (t == 0) {
            uint32_t B = wv[pb][0];
#pragma unroll
            for (int u = 1; u < 8; u++) B = max(B, wv[pb][u]);
            bc[pb] = B;
            out[s] = 4095 - (int)(B & 0xFFFu);
        }
        __syncthreads();
        uint32_t best = bc[pb];
        if (myKey == best) {   // unique owner (index embedded in key)
            int jwin = 4095 - (int)(best & 0xFFFu);
            sc[jwin] = 0;
            uint32_t nk = 0;
#pragma unroll
            for (int q = 0; q < 8; q++)
                nk = max(nk, max(sc[8 * t + q], sc[2048 + 8 * t + q]));
            myKey = nk;
        }
    }
}

// ---------------- 4) pair gather-mean ----------------
__global__ __launch_bounds__(128) void k_pair(const float* __restrict__ br,
                                              const float* __restrict__ bi) {
    __shared__ int sp[256], sq[256];
    int n = blockIdx.y;
    int base = n * PAIRS + blockIdx.x * 256;
    for (int t = threadIdx.x; t < 256; t += 128) {
        sp[t] = g_knn[0][base + t];
        sq[t] = g_knn[1][base + t];
    }
    __syncthreads();
    int c = threadIdx.x;
    float brc = br[c], bic = bi[c];
    float aR = 0.0f, aI = 0.0f;
#pragma unroll 4
    for (int t = 0; t < 256; t++) {
        int p = sp[t], q = sq[t];
        float fr = g_AB[0][p * CCH + c] - g_AB[1][q * CCH + c] + brc;
        aR += (fr >= 0.0f) ? fr : 0.01f * fr;
        float fi = g_AB[2][q * CCH + c] - g_AB[3][p * CCH + c] + bic;
        aI += (fi >= 0.0f) ? fi : 0.01f * fi;
    }
    int b = n * 256 + blockIdx.x;
    g_partial[b][c]       = aR;
    g_partial[b][c + 128] = aI;
}

// ---------------- 5) first-level reduce: 256 partials -> 16 per n ----------------
__global__ void k_reduce16() {
    int b = blockIdx.x;                 // 64 blocks: n = b>>4, group = b&15
    int n = b >> 4, r0 = (b & 15) * 16;
    int d = threadIdx.x;
    float s = 0.0f;
#pragma unroll
    for (int r = 0; r < 16; r++) s += g_partial[n * 256 + r0 + r][d];
    g_p2[b][d] = s;
}

// ---------------- 6) final reduce + SE gate ----------------
__global__ void k_se(const float* __restrict__ w1, const float* __restrict__ b1,
                     const float* __restrict__ w2, const float* __restrict__ b2) {
    __shared__ float m_s[1024];
    __shared__ float tm[NB][8];
    int tid = threadIdx.x;              // 512
#pragma unroll
    for (int it = 0; it < 2; it++) {
        int idx = tid + 512 * it;
        int n = idx >> 8, d = idx & 255;
        float s = 0.0f;
#pragma unroll
        for (int g = 0; g < 16; g++) s += g_p2[n * 16 + g][d];
        m_s[idx] = s * (1.0f / (float)PAIRS);
    }
    __syncthreads();
    if (tid < 32) {
        int n = tid >> 3, j = tid & 7;
        float s = b1[j];
        for (int d = 0; d < 256; d++) s += m_s[n * 256 + d] * w1[d * 8 + j];
        tm[n][j] = (s >= 0.0f) ? s : 0.01f * s;
    }
    __syncthreads();
    int n = tid >> 7, c = tid & 127;
    float s = b2[c];
#pragma unroll
    for (int j = 0; j < 8; j++) s += tm[n][j] * w2[j * 128 + c];
    g_gate[n * 128 + c] = 1.0f / (1.0f + expf(-s));
}

// ---------------- 7) gated blend + relu ----------------
__global__ void k_out(const float* __restrict__ g1, const float* __restrict__ g2,
                      float* __restrict__ out) {
    int o = blockIdx.x * blockDim.x + threadIdx.x;
    if (o >= NB * CCH * HW) return;
    int nc = o >> 12;
    float g = g_gate[nc];
    float v = g1[0] * g * g_pool[0][o] + g2[0] * (1.0f - g) * g_pool[1][o];
    out[o] = fmaxf(v, 0.0f);
}

// ---------------- launch ----------------
extern "C" void kernel_launch(void* const* d_in, const int* in_sizes, int n_in,
                              void* d_out, int out_size) {
    const float* rgb = (const float*)d_in[0];
    const float* ir  = (const float*)d_in[1];
    const float* Wr  = (const float*)d_in[2];
    const float* br  = (const float*)d_in[3];
    const float* Wi  = (const float*)d_in[4];
    const float* bi  = (const float*)d_in[5];
    const float* w1  = (const float*)d_in[6];
    const float* b1  = (const float*)d_in[7];
    const float* w2  = (const float*)d_in[8];
    const float* b2  = (const float*)d_in[9];
    const float* g1  = (const float*)d_in[10];
    const float* g2  = (const float*)d_in[11];
    float* out = (float*)d_out;

    cudaFuncSetAttribute(k_gram_tri, cudaFuncAttributeMaxDynamicSharedMemorySize, GS_TOTAL);

    k_tnorm<<<dim3(128, 4, 2), 256>>>(rgb, ir);        // fused pool+transpose+norm

    k_gram_tri<<<dim3(528, 9), 256, GS_TOTAL>>>(Wr, Wi); // gram tiles (y<8) + ab tables (y==8)
    k_topk<<<dim3(4096, 4, 2), 256>>>();               // pre-ordered keys, R13 loop structure

    k_pair<<<dim3(256, 4), 128>>>(br, bi);
    k_reduce16<<<64, 256>>>();
    k_se<<<1, 512>>>(w1, b1, w2, b2);
    k_out<<<8192, 256>>>(g1, g2, out);
}